// round 2
// baseline (speedup 1.0000x reference)
#include <cuda_runtime.h>
#include <math.h>

#define BB 1024
#define SS 256
#define DD 128
#define HH 512
#define GG 2048          // 4H
#define KPAD 784         // 128 (x_c) + 512 (h) + 128 (m) + 1 (d) padded to 784
#define NIMP (1024*256*128)

typedef unsigned long long ull;

// ---------------- device scratch (no allocations allowed) ----------------
__device__ float g_A[BB*KPAD];        // per-step GEMM input [b, k]
__device__ float g_h[BB*HH];
__device__ float g_c[BB*HH];
__device__ float g_WcatT[KPAD*GG];    // [k][gcol], gcol = 4*j + gate (interleaved)
__device__ float g_biasI[GG];         // bih+bhh, interleaved layout
__device__ float g_Bc[(HH+DD)*DD];    // rows 0..511 = WhrT, rows 512..639 = WfrT
__device__ float g_loss[SS];
__device__ float g_msum[SS];

// ---------------- packed f32x2 helpers (Blackwell) ----------------
__device__ __forceinline__ ull pack2(float lo, float hi){
    ull r; asm("mov.b64 %0, {%1,%2};" : "=l"(r) : "f"(lo), "f"(hi)); return r;
}
__device__ __forceinline__ void unpack2(ull v, float &lo, float &hi){
    asm("mov.b64 {%0,%1}, %2;" : "=f"(lo), "=f"(hi) : "l"(v));
}
__device__ __forceinline__ ull ffma2(ull a, ull b, ull c){
    ull d; asm("fma.rn.f32x2 %0, %1, %2, %3;" : "=l"(d) : "l"(a), "l"(b), "l"(c)); return d;
}
__device__ __forceinline__ float sigmoidf_(float x){ return 1.f/(1.f+expf(-x)); }

__device__ __forceinline__ float block_reduce_sum(float v, float* red){
    int tid = threadIdx.x;
    red[tid] = v; __syncthreads();
    #pragma unroll
    for (int off = 128; off > 0; off >>= 1){
        if (tid < off) red[tid] += red[tid+off];
        __syncthreads();
    }
    return red[0];
}

// ---------------- init: zero state ----------------
__global__ void init_kernel(){
    int stride = gridDim.x*blockDim.x;
    int t = blockIdx.x*blockDim.x + threadIdx.x;
    for (int i=t;i<BB*KPAD;i+=stride) g_A[i]=0.f;
    for (int i=t;i<BB*HH;i+=stride){ g_h[i]=0.f; g_c[i]=0.f; }
    if (t < SS) g_loss[t]=0.f;
}

// ---------------- build packed weights ----------------
__global__ void build_kernel(const float* __restrict__ Wih, const float* __restrict__ Whh,
                             const float* __restrict__ bih, const float* __restrict__ bhh,
                             const float* __restrict__ Whr, const float* __restrict__ Wfr){
    int stride = gridDim.x*blockDim.x;
    int t0 = blockIdx.x*blockDim.x + threadIdx.x;
    const int IN = 2*DD + 1;  // 257
    for (int idx=t0; idx<KPAD*GG; idx+=stride){
        int k = idx >> 11;         // /2048
        int gcol = idx & 2047;
        int j = gcol >> 2, gate = gcol & 3;
        int gs = gate*HH + j;      // source row in Wih/Whh (i,f,g,o chunks)
        float v;
        if (k < DD)            v = Wih[gs*IN + k];                 // x_c part
        else if (k < DD+HH)    v = Whh[gs*HH + (k-DD)];            // h part
        else if (k < 2*DD+HH)  v = Wih[gs*IN + DD + (k-DD-HH)];    // m part
        else if (k == 2*DD+HH) v = Wih[gs*IN + 2*DD];              // d part
        else                   v = 0.f;                            // pad
        g_WcatT[idx] = v;
    }
    for (int gcol=t0; gcol<GG; gcol+=stride){
        int j = gcol>>2, gate = gcol&3; int gs = gate*HH + j;
        g_biasI[gcol] = bih[gs] + bhh[gs];
    }
    for (int idx=t0; idx<(HH+DD)*DD; idx+=stride){
        int k = idx >> 7, n = idx & (DD-1);
        g_Bc[idx] = (k < HH) ? Whr[n*HH + k] : Wfr[n*DD + (k-HH)];
    }
}

// ---------------- per-step mask sums ----------------
__global__ void msum_kernel(const float* __restrict__ masks){
    __shared__ float red[256];
    int s = blockIdx.x;
    float sum = 0.f;
    for (int idx = threadIdx.x; idx < BB*DD; idx += 256){
        int b = idx >> 7, d = idx & (DD-1);
        sum += masks[(size_t)b*SS*DD + (size_t)s*DD + d];
    }
    float tot = block_reduce_sum(sum, red);
    if (threadIdx.x == 0) g_msum[s] = tot;
}

// ---------------- step A: decay h, x_h GEMM, build A ----------------
// grid: 64 blocks (16 rows each), 256 threads; C tile [16 x 128], K = 512
__global__ __launch_bounds__(256,1) void prepA_kernel(
    const float* __restrict__ data, const float* __restrict__ masks,
    const float* __restrict__ deltas, const float* __restrict__ Wtd,
    const float* __restrict__ btd, const float* __restrict__ bhr, int s)
{
    __shared__ float As[16][17];
    __shared__ float Bs[16][132];
    int tid = threadIdx.x;
    int m0 = blockIdx.x * 16;
    int lr = tid >> 4;      // row (0..15) for both load and compute
    int lk = tid & 15;      // k within tile for load
    int tx = tid & 15;      // col group for compute
    int ty = lr;
    float d_b = deltas[(size_t)(m0 + lr)*SS + s];

    ull acc[4] = {0ull,0ull,0ull,0ull};
    for (int k0 = 0; k0 < HH; k0 += 16){
        int k = k0 + lk;
        float hv  = g_h[(size_t)(m0+lr)*HH + k];
        float td  = d_b * Wtd[k] + btd[k];
        float dec = expf(-fmaxf(td, 0.f));
        float hd  = hv * dec;
        As[lk][lr] = hd;
        g_A[(size_t)(m0+lr)*KPAD + DD + k] = hd;   // hdec region of A
        #pragma unroll
        for (int i=0;i<2;i++){
            int idx = i*256 + tid;
            int kk = idx >> 5; int n4 = (idx & 31) << 2;
            *(float4*)&Bs[kk][n4] = *(const float4*)&g_Bc[(size_t)(k0+kk)*DD + n4];
        }
        __syncthreads();
        #pragma unroll
        for (int kk=0; kk<16; kk++){
            float a = As[kk][ty];
            ull a2 = pack2(a, a);
            float4 b01 = *(float4*)&Bs[kk][tx*8];
            float4 b23 = *(float4*)&Bs[kk][tx*8+4];
            acc[0]=ffma2(a2, pack2(b01.x,b01.y), acc[0]);
            acc[1]=ffma2(a2, pack2(b01.z,b01.w), acc[1]);
            acc[2]=ffma2(a2, pack2(b23.x,b23.y), acc[2]);
            acc[3]=ffma2(a2, pack2(b23.z,b23.w), acc[3]);
        }
        __syncthreads();
    }
    int b = m0 + ty;
    const float* xrow = data  + (size_t)b*SS*DD + (size_t)s*DD;
    const float* mrow = masks + (size_t)b*SS*DD + (size_t)s*DD;
    float r[8];
    unpack2(acc[0], r[0], r[1]); unpack2(acc[1], r[2], r[3]);
    unpack2(acc[2], r[4], r[5]); unpack2(acc[3], r[6], r[7]);
    #pragma unroll
    for (int j=0;j<8;j++){
        int n = tx*8 + j;
        float xh = r[j] + bhr[n];
        float x  = xrow[n];
        float m  = mrow[n];
        float xc = m*x + (1.f-m)*xh;
        g_A[(size_t)b*KPAD + n] = xc;
        g_A[(size_t)b*KPAD + DD + HH + n] = m;
    }
    if (tx == 0) g_A[(size_t)b*KPAD + 2*DD + HH] = d_b;
}

// ---------------- gates GEMM + fused LSTM ----------------
// grid: (16, 8), 256 threads; C tile [128 x 128], K = 784
__global__ __launch_bounds__(256,1) void gates_kernel()
{
    __shared__ float As[16][132];
    __shared__ float Bs[16][132];
    int tid = threadIdx.x;
    int tx = tid & 15;
    int ty = tid >> 4;
    int row0 = blockIdx.y * 128;
    int col0 = blockIdx.x * 128;

    ull acc[8][4];
    #pragma unroll
    for (int i=0;i<8;i++)
        #pragma unroll
        for (int j=0;j<4;j++) acc[i][j] = 0ull;

    for (int k0 = 0; k0 < KPAD; k0 += 16){
        #pragma unroll
        for (int i=0;i<2;i++){
            int idx = i*256 + tid;           // 0..511
            int m = idx >> 2;                // 0..127
            int k4 = (idx & 3) << 2;         // 0,4,8,12
            float4 v = *(const float4*)(g_A + (size_t)(row0+m)*KPAD + k0 + k4);
            As[k4+0][m]=v.x; As[k4+1][m]=v.y; As[k4+2][m]=v.z; As[k4+3][m]=v.w;
        }
        #pragma unroll
        for (int i=0;i<2;i++){
            int idx = i*256 + tid;
            int kk = idx >> 5; int n4 = (idx & 31) << 2;
            *(float4*)&Bs[kk][n4] = *(const float4*)(g_WcatT + (size_t)(k0+kk)*GG + col0 + n4);
        }
        __syncthreads();
        #pragma unroll
        for (int kk=0; kk<16; kk++){
            float a[8];
            *(float4*)&a[0] = *(float4*)&As[kk][ty*8];
            *(float4*)&a[4] = *(float4*)&As[kk][ty*8+4];
            float4 b01 = *(float4*)&Bs[kk][tx*8];
            float4 b23 = *(float4*)&Bs[kk][tx*8+4];
            ull b[4];
            b[0]=pack2(b01.x,b01.y); b[1]=pack2(b01.z,b01.w);
            b[2]=pack2(b23.x,b23.y); b[3]=pack2(b23.z,b23.w);
            #pragma unroll
            for (int i=0;i<8;i++){
                ull a2 = pack2(a[i], a[i]);
                #pragma unroll
                for (int j=0;j<4;j++) acc[i][j] = ffma2(a2, b[j], acc[i][j]);
            }
        }
        __syncthreads();
    }

    // fused LSTM epilogue: cols col0+tx*8 .. +7 = gates (i,f,g,o) of h-indices j0, j0+1
    int cbase = col0 + tx*8;
    int j0 = cbase >> 2;
    float bb[8];
    *(float4*)&bb[0] = *(const float4*)&g_biasI[cbase];
    *(float4*)&bb[4] = *(const float4*)&g_biasI[cbase+4];
    #pragma unroll
    for (int i=0;i<8;i++){
        int b = row0 + ty*8 + i;
        float r[8];
        unpack2(acc[i][0], r[0], r[1]); unpack2(acc[i][1], r[2], r[3]);
        unpack2(acc[i][2], r[4], r[5]); unpack2(acc[i][3], r[6], r[7]);
        #pragma unroll
        for (int q=0;q<8;q++) r[q] += bb[q];
        {
            int j = j0;
            float cold = g_c[(size_t)b*HH + j];
            float cn = sigmoidf_(r[1])*cold + sigmoidf_(r[0])*tanhf(r[2]);
            g_c[(size_t)b*HH + j] = cn;
            g_h[(size_t)b*HH + j] = sigmoidf_(r[3])*tanhf(cn);
        }
        {
            int j = j0 + 1;
            float cold = g_c[(size_t)b*HH + j];
            float cn = sigmoidf_(r[5])*cold + sigmoidf_(r[4])*tanhf(r[6]);
            g_c[(size_t)b*HH + j] = cn;
            g_h[(size_t)b*HH + j] = sigmoidf_(r[7])*tanhf(cn);
        }
    }
}

// ---------------- step C: x_h2 & x_f GEMM, outputs, loss ----------------
// grid: 64 blocks, 256 threads; C tile [16 x 128], K = 640 (512 h + 128 x)
__global__ __launch_bounds__(256,1) void stepC_kernel(
    const float* __restrict__ data, const float* __restrict__ masks,
    const float* __restrict__ bhr, const float* __restrict__ bfr,
    float* __restrict__ out, int s)
{
    __shared__ float As[16][17];
    __shared__ float Bs[16][132];
    __shared__ float red[256];
    int tid = threadIdx.x;
    int m0 = blockIdx.x * 16;
    int lr = tid >> 4;
    int lk = tid & 15;
    int tx = tid & 15;
    int ty = lr;

    ull accH[4] = {0ull,0ull,0ull,0ull};
    ull accX[4] = {0ull,0ull,0ull,0ull};

    // part 1: h_new @ WhrT  (k in [0,512))
    for (int k0 = 0; k0 < HH; k0 += 16){
        int k = k0 + lk;
        As[lk][lr] = g_h[(size_t)(m0+lr)*HH + k];
        #pragma unroll
        for (int i=0;i<2;i++){
            int idx = i*256 + tid;
            int kk = idx >> 5; int n4 = (idx & 31) << 2;
            *(float4*)&Bs[kk][n4] = *(const float4*)&g_Bc[(size_t)(k0+kk)*DD + n4];
        }
        __syncthreads();
        #pragma unroll
        for (int kk=0; kk<16; kk++){
            float a = As[kk][ty];
            ull a2 = pack2(a, a);
            float4 b01 = *(float4*)&Bs[kk][tx*8];
            float4 b23 = *(float4*)&Bs[kk][tx*8+4];
            accH[0]=ffma2(a2, pack2(b01.x,b01.y), accH[0]);
            accH[1]=ffma2(a2, pack2(b01.z,b01.w), accH[1]);
            accH[2]=ffma2(a2, pack2(b23.x,b23.y), accH[2]);
            accH[3]=ffma2(a2, pack2(b23.z,b23.w), accH[3]);
        }
        __syncthreads();
    }
    // part 2: x @ WfrT  (k in [512,640))
    for (int k0 = HH; k0 < HH+DD; k0 += 16){
        int k = k0 + lk;
        As[lk][lr] = data[(size_t)(m0+lr)*SS*DD + (size_t)s*DD + (k - HH)];
        #pragma unroll
        for (int i=0;i<2;i++){
            int idx = i*256 + tid;
            int kk = idx >> 5; int n4 = (idx & 31) << 2;
            *(float4*)&Bs[kk][n4] = *(const float4*)&g_Bc[(size_t)(k0+kk)*DD + n4];
        }
        __syncthreads();
        #pragma unroll
        for (int kk=0; kk<16; kk++){
            float a = As[kk][ty];
            ull a2 = pack2(a, a);
            float4 b01 = *(float4*)&Bs[kk][tx*8];
            float4 b23 = *(float4*)&Bs[kk][tx*8+4];
            accX[0]=ffma2(a2, pack2(b01.x,b01.y), accX[0]);
            accX[1]=ffma2(a2, pack2(b01.z,b01.w), accX[1]);
            accX[2]=ffma2(a2, pack2(b23.x,b23.y), accX[2]);
            accX[3]=ffma2(a2, pack2(b23.z,b23.w), accX[3]);
        }
        __syncthreads();
    }

    int b = m0 + ty;
    const float* xrow = data  + (size_t)b*SS*DD + (size_t)s*DD;
    const float* mrow = masks + (size_t)b*SS*DD + (size_t)s*DD;
    float rh[8], rx[8];
    unpack2(accH[0], rh[0], rh[1]); unpack2(accH[1], rh[2], rh[3]);
    unpack2(accH[2], rh[4], rh[5]); unpack2(accH[3], rh[6], rh[7]);
    unpack2(accX[0], rx[0], rx[1]); unpack2(accX[1], rx[2], rx[3]);
    unpack2(accX[2], rx[4], rx[5]); unpack2(accX[3], rx[6], rx[7]);
    float lsum = 0.f;
    #pragma unroll
    for (int j=0;j<8;j++){
        int n = tx*8 + j;
        float xh2 = rh[j] + bhr[n];
        float xf  = rx[j] + bfr[n];
        float x   = xrow[n];
        float m   = mrow[n];
        out[(size_t)b*SS*DD + (size_t)s*DD + n] = m*x + (1.f-m)*(xh2 + xf);
        float e = x - xh2;
        lsum += e*e*m;
    }
    float tot = block_reduce_sum(lsum, red);
    if (tid == 0) atomicAdd(&g_loss[s], tot);
}

// ---------------- final loss ----------------
__global__ void final_kernel(float* __restrict__ out, int out_size){
    __shared__ float red[256];
    int s = threadIdx.x;
    float v = g_loss[s] / (g_msum[s] + 1e-5f);
    float tot = block_reduce_sum(v, red);
    if (s == 0 && out_size > NIMP) out[NIMP] = tot / (float)SS;
}

// ---------------- launch ----------------
extern "C" void kernel_launch(void* const* d_in, const int* in_sizes, int n_in,
                              void* d_out, int out_size){
    const float* data   = (const float*)d_in[0];
    const float* masks  = (const float*)d_in[1];
    const float* deltas = (const float*)d_in[2];
    const float* Wih    = (const float*)d_in[3];
    const float* Whh    = (const float*)d_in[4];
    const float* bih    = (const float*)d_in[5];
    const float* bhh    = (const float*)d_in[6];
    const float* Wtd    = (const float*)d_in[7];
    const float* btd    = (const float*)d_in[8];
    const float* Whr    = (const float*)d_in[9];
    const float* bhr    = (const float*)d_in[10];
    const float* Wfr    = (const float*)d_in[11];
    const float* bfr    = (const float*)d_in[12];
    float* out = (float*)d_out;

    init_kernel<<<512, 256>>>();
    build_kernel<<<512, 256>>>(Wih, Whh, bih, bhh, Whr, Wfr);
    msum_kernel<<<SS, 256>>>(masks);
    for (int s = 0; s < SS; s++){
        prepA_kernel<<<BB/16, 256>>>(data, masks, deltas, Wtd, btd, bhr, s);
        gates_kernel<<<dim3(GG/128, BB/128), 256>>>();
        stepC_kernel<<<BB/16, 256>>>(data, masks, bhr, bfr, out, s);
    }
    final_kernel<<<1, 256>>>(out, out_size);
}

// round 4
// speedup vs baseline: 3.1016x; 3.1016x over previous
#include <cuda_runtime.h>
#include <cuda_bf16.h>
#include <math.h>

#define BB 1024
#define SS 256
#define DD 128
#define HH 512
#define GG 2048
#define KP2 832          // 128 x_c + 512 hdec + 128 m + 1 d + 63 pad = 13*64
#define NCH 13
#define NIMP (1024*256*128)

#define CHK 64
#define RS 72                        // padded smem row stride (elems)
#define TILE_B (128*RS*2)            // 18432 B per matrix tile
#define BUF_B (4*TILE_B)             // Ah,Al,Bh,Bl
#define GATES_SMEM (2*BUF_B)         // 147456 B double-buffered

typedef unsigned long long ull;
typedef unsigned int uint;

__device__ uint4 g_AhV[BB*KP2/8];
__device__ uint4 g_AlV[BB*KP2/8];
__device__ uint4 g_WhV[(size_t)GG*KP2/8];
__device__ uint4 g_WlV[(size_t)GG*KP2/8];
__device__ float g_h[HH*BB];          // [j][b]
__device__ float g_c[HH*BB];          // [j][b]
__device__ float g_Bc[(HH+DD)*DD];    // [k][n]: rows 0..511 WhrT, 512..639 WfrT
__device__ float g_biasI[GG];         // gcol = 4*j + gate
__device__ float g_loss[SS];
__device__ float g_msum[SS];

#define g_Ah ((__nv_bfloat16*)g_AhV)
#define g_Al ((__nv_bfloat16*)g_AlV)
#define g_Wh ((__nv_bfloat16*)g_WhV)
#define g_Wl ((__nv_bfloat16*)g_WlV)

__device__ __forceinline__ ull pack2(float lo, float hi){
    ull r; asm("mov.b64 %0, {%1,%2};" : "=l"(r) : "f"(lo), "f"(hi)); return r;
}
__device__ __forceinline__ void unpack2(ull v, float &lo, float &hi){
    asm("mov.b64 {%0,%1}, %2;" : "=f"(lo), "=f"(hi) : "l"(v));
}
__device__ __forceinline__ ull ffma2(ull a, ull b, ull c){
    ull d; asm("fma.rn.f32x2 %0, %1, %2, %3;" : "=l"(d) : "l"(a), "l"(b), "l"(c)); return d;
}
__device__ __forceinline__ float sigmoidf_(float x){ return 1.f/(1.f+expf(-x)); }
__device__ __forceinline__ uint smem_u32(const void* p){
    uint a; asm("{ .reg .u64 t; cvta.to.shared.u64 t, %1; cvt.u32.u64 %0, t; }" : "=r"(a) : "l"(p));
    return a;
}
__device__ __forceinline__ void bsplit(float v, __nv_bfloat16 &h, __nv_bfloat16 &l){
    h = __float2bfloat16(v);
    l = __float2bfloat16(v - __bfloat162float(h));
}
__device__ __forceinline__ void cp16(uint dst, const void* src){
    asm volatile("cp.async.cg.shared.global [%0], [%1], 16;" :: "r"(dst), "l"(src));
}
#define CP_COMMIT() asm volatile("cp.async.commit_group;" ::: "memory")
#define CP_WAIT1()  asm volatile("cp.async.wait_group 1;" ::: "memory")
#define CP_WAIT0()  asm volatile("cp.async.wait_group 0;" ::: "memory")

__device__ __forceinline__ void mma16816(float* c, const uint* a, uint b0, uint b1){
    asm volatile("mma.sync.aligned.m16n8k16.row.col.f32.bf16.bf16.f32 "
        "{%0,%1,%2,%3}, {%4,%5,%6,%7}, {%8,%9}, {%0,%1,%2,%3};"
        : "+f"(c[0]), "+f"(c[1]), "+f"(c[2]), "+f"(c[3])
        : "r"(a[0]), "r"(a[1]), "r"(a[2]), "r"(a[3]), "r"(b0), "r"(b1));
}
__device__ __forceinline__ uint lds32(const __nv_bfloat16* p){
    return *(const uint*)p;
}

// ---------------- init ----------------
__global__ void init_kernel(const float* __restrict__ data, const float* __restrict__ masks,
                            const float* __restrict__ deltas, const float* __restrict__ bhr){
    int t = blockIdx.x*blockDim.x + threadIdx.x;
    int stride = gridDim.x*blockDim.x;
    for (int idx=t; idx<BB*KP2; idx+=stride){
        int b = idx/KP2, k = idx - b*KP2;
        float v = 0.f;
        if (k < DD){
            float m = masks[(size_t)b*SS*DD + k];
            v = m*data[(size_t)b*SS*DD + k] + (1.f-m)*bhr[k];
        } else if (k >= DD+HH && k < 2*DD+HH){
            v = masks[(size_t)b*SS*DD + (k-DD-HH)];
        } else if (k == 2*DD+HH){
            v = deltas[(size_t)b*SS];
        }
        __nv_bfloat16 h, l; bsplit(v, h, l);
        g_Ah[idx] = h; g_Al[idx] = l;
    }
    for (int i=t;i<HH*BB;i+=stride) g_c[i]=0.f;
    if (t < SS) g_loss[t]=0.f;
}

// ---------------- build packed weights ----------------
__global__ void build_kernel(const float* __restrict__ Wih, const float* __restrict__ Whh,
                             const float* __restrict__ bih, const float* __restrict__ bhh,
                             const float* __restrict__ Whr, const float* __restrict__ Wfr){
    int t0 = blockIdx.x*blockDim.x + threadIdx.x;
    int stride = gridDim.x*blockDim.x;
    const int IN = 2*DD + 1;
    for (size_t idx=t0; idx<(size_t)GG*KP2; idx+=stride){
        int gcol = (int)(idx / KP2);
        int k    = (int)(idx - (size_t)gcol*KP2);
        int j = gcol >> 2, gate = gcol & 3;
        int gs = gate*HH + j;
        float v = 0.f;
        if (k < DD)            v = Wih[(size_t)gs*IN + k];
        else if (k < DD+HH)    v = Whh[(size_t)gs*HH + (k-DD)];
        else if (k < 2*DD+HH)  v = Wih[(size_t)gs*IN + DD + (k-DD-HH)];
        else if (k == 2*DD+HH) v = Wih[(size_t)gs*IN + 2*DD];
        __nv_bfloat16 h, l; bsplit(v, h, l);
        g_Wh[idx] = h; g_Wl[idx] = l;
    }
    for (int gcol=t0; gcol<GG; gcol+=stride){
        int j = gcol>>2, gate = gcol&3; int gs = gate*HH + j;
        g_biasI[gcol] = bih[gs] + bhh[gs];
    }
    for (int idx=t0; idx<(HH+DD)*DD; idx+=stride){
        int k = idx >> 7, n = idx & (DD-1);
        g_Bc[idx] = (k < HH) ? Whr[(size_t)n*HH + k] : Wfr[(size_t)n*DD + (k-HH)];
    }
}

__global__ void msum_kernel(const float* __restrict__ masks){
    __shared__ float red[256];
    int s = blockIdx.x;
    float sum = 0.f;
    for (int idx = threadIdx.x; idx < BB*DD; idx += 256){
        int b = idx >> 7, d = idx & (DD-1);
        sum += masks[(size_t)b*SS*DD + (size_t)s*DD + d];
    }
    red[threadIdx.x] = sum; __syncthreads();
    #pragma unroll
    for (int off=128; off>0; off>>=1){
        if (threadIdx.x < off) red[threadIdx.x] += red[threadIdx.x+off];
        __syncthreads();
    }
    if (threadIdx.x == 0) g_msum[s] = red[0];
}

// ---------------- gates: HMMA bf16 3-split GEMM + fused LSTM ----------------
__device__ __forceinline__ void issue_chunk(uint sb, int buf, int kc,
    const __nv_bfloat16* pAh, const __nv_bfloat16* pAl,
    const __nv_bfloat16* pBh, const __nv_bfloat16* pBl, int tid){
    uint base = sb + buf*BUF_B;
    const __nv_bfloat16* ps[4] = {pAh, pAl, pBh, pBl};
    #pragma unroll
    for (int i = 0; i < 16; i++){
        int lin = i*256 + tid;
        int p = i >> 2;                   // 1024 ops per matrix
        int r = (lin >> 3) & 127;
        int u = lin & 7;
        uint dst = base + p*TILE_B + (uint)(r*RS + u*8)*2;
        cp16(dst, ps[p] + (size_t)r*KP2 + kc + u*8);
    }
}

__global__ __launch_bounds__(256,1) void gates_kernel(){
    extern __shared__ __align__(16) char smem[];
    uint sb = smem_u32(smem);
    int tid = threadIdx.x;
    int w   = tid >> 5;
    int lane = tid & 31;
    int g  = lane >> 2;       // groupID
    int t2 = lane & 3;        // threadID in group
    int wm = w & 3;           // warp M index (rows wm*32)
    int wn = w >> 2;          // warp N index (cols wn*64)
    int row0 = blockIdx.y * 128;
    int col0 = blockIdx.x * 128;

    const __nv_bfloat16* pAh = g_Ah + (size_t)row0*KP2;
    const __nv_bfloat16* pAl = g_Al + (size_t)row0*KP2;
    const __nv_bfloat16* pBh = g_Wh + (size_t)col0*KP2;
    const __nv_bfloat16* pBl = g_Wl + (size_t)col0*KP2;

    float acc[64];
    #pragma unroll
    for (int i = 0; i < 64; i++) acc[i] = 0.f;

    issue_chunk(sb, 0, 0, pAh, pAl, pBh, pBl, tid);
    CP_COMMIT();

    for (int ch = 0; ch < NCH; ch++){
        if (ch < NCH-1){
            issue_chunk(sb, (ch+1)&1, (ch+1)*CHK, pAh, pAl, pBh, pBl, tid);
            CP_COMMIT();
            CP_WAIT1();
        } else {
            CP_WAIT0();
        }
        __syncthreads();

        const __nv_bfloat16* Ah_s = (const __nv_bfloat16*)(smem + (ch&1)*BUF_B);
        const __nv_bfloat16* Al_s = Ah_s + TILE_B/2;
        const __nv_bfloat16* Bh_s = Ah_s + TILE_B;      // 2 tiles in elems
        const __nv_bfloat16* Bl_s = Ah_s + TILE_B*3/2;

        #pragma unroll
        for (int kk = 0; kk < 4; kk++){
            int ks = kk*16 + t2*2;
            uint ah[2][4], al[2][4];
            #pragma unroll
            for (int ma = 0; ma < 2; ma++){
                int r0 = (wm*32 + ma*16 + g)*RS;
                int r1 = r0 + 8*RS;
                ah[ma][0] = lds32(Ah_s + r0 + ks);
                ah[ma][1] = lds32(Ah_s + r1 + ks);
                ah[ma][2] = lds32(Ah_s + r0 + ks + 8);
                ah[ma][3] = lds32(Ah_s + r1 + ks + 8);
                al[ma][0] = lds32(Al_s + r0 + ks);
                al[ma][1] = lds32(Al_s + r1 + ks);
                al[ma][2] = lds32(Al_s + r0 + ks + 8);
                al[ma][3] = lds32(Al_s + r1 + ks + 8);
            }
            #pragma unroll
            for (int na = 0; na < 8; na++){
                int rb = (wn*64 + na*8 + g)*RS;
                uint bh0 = lds32(Bh_s + rb + ks);
                uint bh1 = lds32(Bh_s + rb + ks + 8);
                uint bl0 = lds32(Bl_s + rb + ks);
                uint bl1 = lds32(Bl_s + rb + ks + 8);
                #pragma unroll
                for (int ma = 0; ma < 2; ma++){
                    float* c = &acc[(ma*8 + na)*4];
                    mma16816(c, ah[ma], bh0, bh1);
                    mma16816(c, ah[ma], bl0, bl1);
                    mma16816(c, al[ma], bh0, bh1);
                }
            }
        }
        __syncthreads();
    }

    // fused LSTM epilogue
    #pragma unroll
    for (int ma = 0; ma < 2; ma++){
        #pragma unroll
        for (int na = 0; na < 8; na++){
            float* c = &acc[(ma*8 + na)*4];
            int nb = col0 + wn*64 + na*8;
            int gc = nb + t2*2;
            float2 bi = *(const float2*)&g_biasI[gc];
            c[0] += bi.x; c[1] += bi.y; c[2] += bi.x; c[3] += bi.y;
            float p0 = __shfl_xor_sync(0xFFFFFFFFu, c[0], 1);
            float p1 = __shfl_xor_sync(0xFFFFFFFFu, c[1], 1);
            float p2 = __shfl_xor_sync(0xFFFFFFFFu, c[2], 1);
            float p3 = __shfl_xor_sync(0xFFFFFFFFu, c[3], 1);
            int j = (nb >> 2) + (t2 >> 1);
            int row = wm*32 + ma*16 + g + ((t2 & 1) ? 8 : 0);
            float gi, gf, gg, go;
            if ((t2 & 1) == 0){ gi = c[0]; gf = c[1]; gg = p0; go = p1; }
            else              { gi = p2;   gf = p3;   gg = c[2]; go = c[3]; }
            int b = row0 + row;
            size_t o = (size_t)j*BB + b;
            float cold = g_c[o];
            float cn = sigmoidf_(gf)*cold + sigmoidf_(gi)*tanhf(gg);
            g_c[o] = cn;
            g_h[o] = sigmoidf_(go)*tanhf(cn);
        }
    }
}

// ---------------- mid: stepC(s) + prepA(s+1) fused ----------------
__global__ __launch_bounds__(256,1) void mid_kernel(
    const float* __restrict__ data, const float* __restrict__ masks,
    const float* __restrict__ deltas, const float* __restrict__ Wtd,
    const float* __restrict__ btd, const float* __restrict__ bhr,
    const float* __restrict__ bfr, float* __restrict__ out, int s)
{
    __shared__ float sh_h[8][516];
    __shared__ float sh_hd[8][516];
    __shared__ float sh_x[8][128];
    __shared__ float Bs[16][132];
    __shared__ float red[256];
    __shared__ float sh_d[8];
    int tid = threadIdx.x;
    int m0 = blockIdx.x * 8;
    int tx = tid & 31, ty = tid >> 5;
    bool hasNext = (s+1 < SS);

    if (tid < 8) sh_d[tid] = hasNext ? deltas[(size_t)(m0+tid)*SS + s + 1] : 0.f;
    __syncthreads();

    #pragma unroll 4
    for (int i = 0; i < 16; i++){
        int lin = i*256 + tid;
        int k = lin >> 3, r = lin & 7;
        float hv = g_h[(size_t)k*BB + m0 + r];
        sh_h[r][k] = hv;
        float hd = 0.f;
        if (hasNext){
            float td = sh_d[r]*Wtd[k] + btd[k];
            hd = hv * expf(-fmaxf(td, 0.f));
        }
        sh_hd[r][k] = hd;
    }
    {
        int r = tid >> 5, n4 = (tid & 31) << 2;
        *(float4*)&sh_x[r][n4] = *(const float4*)&data[((size_t)(m0+r)*SS + s)*DD + n4];
    }
    __syncthreads();

    if (hasNext){
        int r = tid >> 5, lw = tid & 31, k0 = lw*16;
        __align__(16) __nv_bfloat16 th[16], tl[16];
        #pragma unroll
        for (int q = 0; q < 16; q++) bsplit(sh_hd[r][k0+q], th[q], tl[q]);
        size_t off = (size_t)(m0+r)*KP2 + DD + k0;
        *(uint4*)(g_Ah+off)   = *(uint4*)th;
        *(uint4*)(g_Ah+off+8) = *(uint4*)(th+8);
        *(uint4*)(g_Al+off)   = *(uint4*)tl;
        *(uint4*)(g_Al+off+8) = *(uint4*)(tl+8);
    }

    ull aH[2]={0,0}, aD[2]={0,0}, aX[2]={0,0};
    for (int k0 = 0; k0 < HH+DD; k0 += 16){
        #pragma unroll
        for (int i = 0; i < 2; i++){
            int lin = i*256 + tid;
            int kk = lin >> 5, n4 = (lin & 31) << 2;
            *(float4*)&Bs[kk][n4] = *(const float4*)&g_Bc[(size_t)(k0+kk)*DD + n4];
        }
        __syncthreads();
        if (k0 < HH){
            #pragma unroll
            for (int kk = 0; kk < 16; kk++){
                float4 bv = *(float4*)&Bs[kk][tx*4];
                ull b0 = pack2(bv.x, bv.y), b1 = pack2(bv.z, bv.w);
                float ah = sh_h[ty][k0+kk];  ull a2 = pack2(ah, ah);
                aH[0] = ffma2(a2, b0, aH[0]); aH[1] = ffma2(a2, b1, aH[1]);
                float ad = sh_hd[ty][k0+kk]; ull d2 = pack2(ad, ad);
                aD[0] = ffma2(d2, b0, aD[0]); aD[1] = ffma2(d2, b1, aD[1]);
            }
        } else {
            #pragma unroll
            for (int kk = 0; kk < 16; kk++){
                float4 bv = *(float4*)&Bs[kk][tx*4];
                float ax = sh_x[ty][k0-HH+kk]; ull a2 = pack2(ax, ax);
                aX[0] = ffma2(a2, pack2(bv.x,bv.y), aX[0]);
                aX[1] = ffma2(a2, pack2(bv.z,bv.w), aX[1]);
            }
        }
        __syncthreads();
    }

    int b = m0 + ty, n0 = tx*4;
    float h2[4], xf[4], hd[4];
    unpack2(aH[0], h2[0], h2[1]); unpack2(aH[1], h2[2], h2[3]);
    unpack2(aX[0], xf[0], xf[1]); unpack2(aX[1], xf[2], xf[3]);
    unpack2(aD[0], hd[0], hd[1]); unpack2(aD[1], hd[2], hd[3]);
    float4 brv = *(const float4*)&bhr[n0];
    float4 frv = *(const float4*)&bfr[n0];
    float4 xv  = *(const float4*)&data [((size_t)b*SS + s)*DD + n0];
    float4 mv  = *(const float4*)&masks[((size_t)b*SS + s)*DD + n0];
    float brr[4]={brv.x,brv.y,brv.z,brv.w}, frr[4]={frv.x,frv.y,frv.z,frv.w};
    float xr[4]={xv.x,xv.y,xv.z,xv.w},      mr[4]={mv.x,mv.y,mv.z,mv.w};
    float lsum = 0.f, ov[4];
    #pragma unroll
    for (int q = 0; q < 4; q++){
        float xh2 = h2[q] + brr[q];
        float xff = xf[q] + frr[q];
        ov[q] = mr[q]*xr[q] + (1.f-mr[q])*(xh2 + xff);
        float e = xr[q] - xh2;
        lsum += e*e*mr[q];
    }
    *(float4*)&out[((size_t)b*SS + s)*DD + n0] = make_float4(ov[0], ov[1], ov[2], ov[3]);

    if (hasNext){
        float4 xn = *(const float4*)&data [((size_t)b*SS + s+1)*DD + n0];
        float4 mn = *(const float4*)&masks[((size_t)b*SS + s+1)*DD + n0];
        float xnr[4]={xn.x,xn.y,xn.z,xn.w}, mnr[4]={mn.x,mn.y,mn.z,mn.w};
        __align__(8) __nv_bfloat16 ah4[4], al4[4], mh4[4], ml4[4];
        #pragma unroll
        for (int q = 0; q < 4; q++){
            float xh = hd[q] + brr[q];
            float xc = mnr[q]*xnr[q] + (1.f-mnr[q])*xh;
            bsplit(xc, ah4[q], al4[q]);
            bsplit(mnr[q], mh4[q], ml4[q]);
        }
        size_t ob = (size_t)b*KP2 + n0;
        *(uint2*)(g_Ah + ob) = *(uint2*)ah4;
        *(uint2*)(g_Al + ob) = *(uint2*)al4;
        size_t om = (size_t)b*KP2 + DD + HH + n0;
        *(uint2*)(g_Ah + om) = *(uint2*)mh4;
        *(uint2*)(g_Al + om) = *(uint2*)ml4;
        if (tx == 0){
            __nv_bfloat16 dh, dl; bsplit(sh_d[ty], dh, dl);
            g_Ah[(size_t)b*KP2 + 2*DD + HH] = dh;
            g_Al[(size_t)b*KP2 + 2*DD + HH] = dl;
        }
    }

    red[tid] = lsum; __syncthreads();
    #pragma unroll
    for (int off = 128; off > 0; off >>= 1){
        if (tid < off) red[tid] += red[tid+off];
        __syncthreads();
    }
    if (tid == 0) atomicAdd(&g_loss[s], red[0]);
}

__global__ void final_kernel(float* __restrict__ out, int out_size){
    __shared__ float red[256];
    int s = threadIdx.x;
    red[s] = g_loss[s] / (g_msum[s] + 1e-5f);
    __syncthreads();
    #pragma unroll
    for (int off = 128; off > 0; off >>= 1){
        if (s < off) red[s] += red[s+off];
        __syncthreads();
    }
    if (s == 0 && out_size > NIMP) out[NIMP] = red[0] / (float)SS;
}

extern "C" void kernel_launch(void* const* d_in, const int* in_sizes, int n_in,
                              void* d_out, int out_size){
    const float* data   = (const float*)d_in[0];
    const float* masks  = (const float*)d_in[1];
    const float* deltas = (const float*)d_in[2];
    const float* Wih    = (const float*)d_in[3];
    const float* Whh    = (const float*)d_in[4];
    const float* bih    = (const float*)d_in[5];
    const float* bhh    = (const float*)d_in[6];
    const float* Wtd    = (const float*)d_in[7];
    const float* btd    = (const float*)d_in[8];
    const float* Whr    = (const float*)d_in[9];
    const float* bhr    = (const float*)d_in[10];
    const float* Wfr    = (const float*)d_in[11];
    const float* bfr    = (const float*)d_in[12];
    float* out = (float*)d_out;

    cudaFuncSetAttribute(gates_kernel, cudaFuncAttributeMaxDynamicSharedMemorySize, GATES_SMEM);

    init_kernel<<<512, 256>>>(data, masks, deltas, bhr);
    build_kernel<<<512, 256>>>(Wih, Whh, bih, bhh, Whr, Wfr);
    msum_kernel<<<SS, 256>>>(masks);
    for (int s = 0; s < SS; s++){
        gates_kernel<<<dim3(16, 8), 256, GATES_SMEM>>>();
        mid_kernel<<<BB/8, 256>>>(data, masks, deltas, Wtd, btd, bhr, bfr, out, s);
    }
    final_kernel<<<1, 256>>>(out, out_size);
}